// round 16
// baseline (speedup 1.0000x reference)
#include <cuda_runtime.h>
#include <math.h>
#include <stdint.h>
#include <stddef.h>

typedef unsigned long long ull;

// ---------------------------------------------------------------------------
// Shapes: B=32, S=1024, WIN=1024, E=128, H=512, L=3
// ---------------------------------------------------------------------------

// ------------------------- device scratch (no allocs) ----------------------
__device__ float g_embed[(size_t)32768 * 128];        // (B*S, E)
__device__ float g_a1v[(size_t)32768 * 128];          // (B*S, E)
__device__ float g_attn[(size_t)32768 * 3];           // logits (B*S, 3)
__device__ float g_attnT[(size_t)1024 * 3 * 32];      // [t][i][b] softmaxed
__device__ float g_xp[(size_t)32768 * 2048];          // (B*S, 4H) gate pre-act
__device__ float g_encT[(size_t)1025 * 16384];        // [t+1][j*32+b]; slot0 = h0
__device__ float g_ctxT[(size_t)1024 * 16384];        // [t][j*32+b]
__device__ float g_hdecT[(size_t)1025 * 16384];       // decoder h, slot per step
__device__ float g_wo1T[512 * 128];                   // W_o1 transposed [k][e]
__device__ float g_be[2048];                          // bih_e + bhh_e
__device__ ull g_pq[32];                              // packed (tag<<32)|p_bits
__device__ unsigned g_arr0[128], g_arr1[128];
__device__ unsigned g_go0, g_go1;

// ------------------------- packed f32x2 helpers -----------------------------
#define FMA2(d, a, b, c) asm("fma.rn.f32x2 %0, %1, %2, %3;" : "=l"(d) : "l"(a), "l"(b), "l"(c))
#define ADD2(d, a, b)    asm("add.rn.f32x2 %0, %1, %2;"     : "=l"(d) : "l"(a), "l"(b))

__device__ __forceinline__ float2 u2f2(ull v) {
    float2 f;
    f.x = __uint_as_float((unsigned)v);
    f.y = __uint_as_float((unsigned)(v >> 32));
    return f;
}
__device__ __forceinline__ ull dupf(float v) {
    ull u = (ull)__float_as_uint(v);
    return u | (u << 32);
}
__device__ __forceinline__ ull packf(float lo, float hi) {
    return (ull)__float_as_uint(lo) | ((ull)__float_as_uint(hi) << 32);
}
__device__ __forceinline__ float fsig(float x) { return 1.0f / (1.0f + __expf(-x)); }
__device__ __forceinline__ float ftanh(float x) {
    float t = __expf(-2.0f * fabsf(x));
    return copysignf((1.0f - t) / (1.0f + t), x);
}

// ------------------------- split-phase grid barrier -------------------------
__device__ __forceinline__ void bar_arrive(unsigned* arr, unsigned tag) {
    __syncthreads();
    __threadfence();
    if (blockIdx.x != 0 && threadIdx.x == 0)
        *((volatile unsigned*)&arr[blockIdx.x]) = tag;
}

__device__ __forceinline__ void bar_wait(unsigned* arr, unsigned* go, unsigned tag) {
    if (blockIdx.x == 0) {
        if (threadIdx.x > 0 && threadIdx.x < 128) {
            while (*((volatile unsigned*)&arr[threadIdx.x]) < tag) {}
        }
        __syncthreads();
        if (threadIdx.x == 0) *((volatile unsigned*)go) = tag;
    } else {
        if (threadIdx.x == 0) {
            while (*((volatile unsigned*)go) < tag) {}
            __threadfence();
        }
        __syncthreads();
    }
}

// ------------------------- prep / init -------------------------------------
__global__ void prep_k(const float* __restrict__ bih_e, const float* __restrict__ bhh_e) {
    int n = blockIdx.x * 256 + threadIdx.x;
    if (n < 2048) g_be[n] = bih_e[n] + bhh_e[n];
}

__global__ void wo1t_k(const float* __restrict__ W_o1) {
    int n = blockIdx.x * 256 + threadIdx.x;   // 65536 elems
    int e = n >> 9, k = n & 511;
    g_wo1T[k * 128 + e] = W_o1[n];
}

__global__ void init_k(const float* __restrict__ enc_h0, const float* __restrict__ dec_h0) {
    int n = blockIdx.x * blockDim.x + threadIdx.x;
    int stride = gridDim.x * blockDim.x;
    if (n < 128) { g_arr0[n] = 0u; g_arr1[n] = 0u; }
    if (n < 32)  g_pq[n] = 0ull;
    if (n == 0) { g_go0 = 0u; g_go1 = 0u; }
    for (int e = n; e < 16384; e += stride) {
        g_encT[e]   = enc_h0[e >> 5];
        g_hdecT[e]  = dec_h0[e >> 5];
    }
}

// ------------------------- generic fp32 GEMM --------------------------------
__global__ void __launch_bounds__(256) gemm_k(const float* __restrict__ A,
                                              const float* __restrict__ W,
                                              const float* __restrict__ bias,
                                              float* __restrict__ C,
                                              int M, int N, int K, int relu) {
    __shared__ float As[16][72];
    __shared__ float Ws[16][72];
    int tid = threadIdx.x;
    int tx = tid & 15, ty = tid >> 4;
    int m0 = blockIdx.x * 64, n0 = blockIdx.y * 64;
    int lr = tid >> 2, lc = (tid & 3) << 2;
    const float* Ap = A + (size_t)(m0 + lr) * K + lc;
    const float* Wp = W + (size_t)(n0 + lr) * K + lc;
    float acc[4][4] = {};
    for (int k0 = 0; k0 < K; k0 += 16) {
        float4 a4 = *(const float4*)(Ap + k0);
        float4 w4 = *(const float4*)(Wp + k0);
        __syncthreads();
        As[lc + 0][lr] = a4.x; As[lc + 1][lr] = a4.y; As[lc + 2][lr] = a4.z; As[lc + 3][lr] = a4.w;
        Ws[lc + 0][lr] = w4.x; Ws[lc + 1][lr] = w4.y; Ws[lc + 2][lr] = w4.z; Ws[lc + 3][lr] = w4.w;
        __syncthreads();
#pragma unroll
        for (int kk = 0; kk < 16; kk++) {
            float4 av = *(const float4*)&As[kk][ty << 2];
            float4 wv = *(const float4*)&Ws[kk][tx << 2];
            acc[0][0] = fmaf(av.x, wv.x, acc[0][0]); acc[0][1] = fmaf(av.x, wv.y, acc[0][1]);
            acc[0][2] = fmaf(av.x, wv.z, acc[0][2]); acc[0][3] = fmaf(av.x, wv.w, acc[0][3]);
            acc[1][0] = fmaf(av.y, wv.x, acc[1][0]); acc[1][1] = fmaf(av.y, wv.y, acc[1][1]);
            acc[1][2] = fmaf(av.y, wv.z, acc[1][2]); acc[1][3] = fmaf(av.y, wv.w, acc[1][3]);
            acc[2][0] = fmaf(av.z, wv.x, acc[2][0]); acc[2][1] = fmaf(av.z, wv.y, acc[2][1]);
            acc[2][2] = fmaf(av.z, wv.z, acc[2][2]); acc[2][3] = fmaf(av.z, wv.w, acc[2][3]);
            acc[3][0] = fmaf(av.w, wv.x, acc[3][0]); acc[3][1] = fmaf(av.w, wv.y, acc[3][1]);
            acc[3][2] = fmaf(av.w, wv.z, acc[3][2]); acc[3][3] = fmaf(av.w, wv.w, acc[3][3]);
        }
    }
    float4 bz = *(const float4*)(bias + n0 + (tx << 2));
#pragma unroll
    for (int i = 0; i < 4; i++) {
        float4 o;
        o.x = acc[i][0] + bz.x; o.y = acc[i][1] + bz.y;
        o.z = acc[i][2] + bz.z; o.w = acc[i][3] + bz.w;
        if (relu) {
            o.x = fmaxf(o.x, 0.f); o.y = fmaxf(o.y, 0.f);
            o.z = fmaxf(o.z, 0.f); o.w = fmaxf(o.w, 0.f);
        }
        *(float4*)(C + (size_t)(m0 + (ty << 2) + i) * N + n0 + (tx << 2)) = o;
    }
}

// ------------------------- attention logits (L=3) ---------------------------
__global__ void logits_k(const float* __restrict__ W_a2, const float* __restrict__ b_a2) {
    __shared__ float w[3][128];
    int tt = threadIdx.x;
    if (tt < 128) { w[0][tt] = W_a2[tt]; w[1][tt] = W_a2[128 + tt]; w[2][tt] = W_a2[256 + tt]; }
    __syncthreads();
    int m = blockIdx.x * 256 + tt;
    const float* row = g_a1v + (size_t)m * 128;
    float s0 = b_a2[0], s1 = b_a2[1], s2 = b_a2[2];
#pragma unroll 4
    for (int k = 0; k < 128; k++) {
        float v = row[k];
        s0 = fmaf(v, w[0][k], s0);
        s1 = fmaf(v, w[1][k], s1);
        s2 = fmaf(v, w[2][k], s2);
    }
    g_attn[(size_t)m * 3 + 0] = s0;
    g_attn[(size_t)m * 3 + 1] = s1;
    g_attn[(size_t)m * 3 + 2] = s2;
}

// ------------------------- softmax over TIME (axis=1) -----------------------
__global__ void softmax_k() {
    int b = blockIdx.x, l = blockIdx.y, tt = threadIdx.x;
    __shared__ float red[256];
    float v[4];
    float mx = -1e30f;
#pragma unroll
    for (int i = 0; i < 4; i++) {
        int t = tt + i * 256;
        v[i] = g_attn[((size_t)b * 1024 + t) * 3 + l];
        mx = fmaxf(mx, v[i]);
    }
    red[tt] = mx; __syncthreads();
    for (int s = 128; s > 0; s >>= 1) { if (tt < s) red[tt] = fmaxf(red[tt], red[tt + s]); __syncthreads(); }
    mx = red[0]; __syncthreads();
    float sm = 0.f;
#pragma unroll
    for (int i = 0; i < 4; i++) { v[i] = expf(v[i] - mx); sm += v[i]; }
    red[tt] = sm; __syncthreads();
    for (int s = 128; s > 0; s >>= 1) { if (tt < s) red[tt] += red[tt + s]; __syncthreads(); }
    float inv = 1.f / red[0];
#pragma unroll
    for (int i = 0; i < 4; i++) {
        int t = tt + i * 256;
        g_attnT[((size_t)t * 3 + l) * 32 + b] = v[i] * inv;
    }
}

// ------------------------- encoder LSTM (persistent, f32x2 packed) ----------
// Threads: bp = tt&15 (batch pair), jl = (tt>>4)&3, q4 = tt>>6 (k quarter)
extern __shared__ float dsm[];
__global__ void __launch_bounds__(256, 1) enc_k(const float* __restrict__ Whh_e,
                                                const float* __restrict__ enc_c0) {
    float* Wsd = dsm;                      // 16 rows x 512 k x 2(dup) = 16384 floats
    __shared__ ull sredq[3 * 256];
    int tt = threadIdx.x, bid = blockIdx.x;
    int bp = tt & 15, jl = (tt >> 4) & 3, q4 = tt >> 6;
    int j = bid * 4 + jl;
    for (int idx = tt; idx < 16 * 512; idx += 256) {
        int r = idx >> 9, k = idx & 511;
        int g = r & 3, jj = bid * 4 + (r >> 2);
        float w = Whh_e[(size_t)(g * 512 + jj) * 512 + k];
        Wsd[r * 1024 + 2 * k] = w;
        Wsd[r * 1024 + 2 * k + 1] = w;
    }
    float2 cc;
    { float cv = enc_c0[j]; cc = make_float2(cv, cv); }
    const ulonglong2* W0 = (const ulonglong2*)&Wsd[(jl * 4 + 0) * 1024];
    const ulonglong2* W1 = (const ulonglong2*)&Wsd[(jl * 4 + 1) * 1024];
    const ulonglong2* W2 = (const ulonglong2*)&Wsd[(jl * 4 + 2) * 1024];
    const ulonglong2* W3 = (const ulonglong2*)&Wsd[(jl * 4 + 3) * 1024];
    int mbeg = q4 * 64;
    __syncthreads();
    for (int t = 0; t < 1024; t++) {
        ull a0, a1, a2, a3;
        if (q4 == 0) {
            // x-gate preacts from g_xp (B*S,4H) layout; issued before bar_wait
            const float* xb0 = g_xp + ((size_t)(2 * bp) * 1024 + t) * 2048;
            const float* xb1 = g_xp + ((size_t)(2 * bp + 1) * 1024 + t) * 2048;
            a0 = packf(xb0[0 * 512 + j], xb1[0 * 512 + j]);
            a1 = packf(xb0[1 * 512 + j], xb1[1 * 512 + j]);
            a2 = packf(xb0[2 * 512 + j], xb1[2 * 512 + j]);
            a3 = packf(xb0[3 * 512 + j], xb1[3 * 512 + j]);
        } else { a0 = a1 = a2 = a3 = 0ull; }
        if (t > 0) bar_wait(g_arr0, &g_go0, (unsigned)t);
        const ull* hp = (const ull*)(g_encT + (size_t)t * 16384) + bp;
#pragma unroll 4
        for (int m = mbeg; m < mbeg + 64; m++) {
            ulonglong2 w0 = W0[m], w1 = W1[m], w2 = W2[m], w3 = W3[m];
            ull x0 = hp[(size_t)(2 * m) * 16];
            ull x1 = hp[(size_t)(2 * m + 1) * 16];
            FMA2(a0, w0.x, x0, a0); FMA2(a0, w0.y, x1, a0);
            FMA2(a1, w1.x, x0, a1); FMA2(a1, w1.y, x1, a1);
            FMA2(a2, w2.x, x0, a2); FMA2(a2, w2.y, x1, a2);
            FMA2(a3, w3.x, x0, a3); FMA2(a3, w3.y, x1, a3);
        }
        if (q4) {
            int o = ((q4 - 1) * 64 + (tt & 63)) * 4;
            sredq[o + 0] = a0; sredq[o + 1] = a1; sredq[o + 2] = a2; sredq[o + 3] = a3;
        }
        __syncthreads();
        if (q4 == 0) {
            int o = tt * 4;
#pragma unroll
            for (int r = 0; r < 3; r++) {
                ADD2(a0, a0, sredq[r * 256 + o + 0]);
                ADD2(a1, a1, sredq[r * 256 + o + 1]);
                ADD2(a2, a2, sredq[r * 256 + o + 2]);
                ADD2(a3, a3, sredq[r * 256 + o + 3]);
            }
            float2 A0 = u2f2(a0), A1 = u2f2(a1), A2 = u2f2(a2), A3 = u2f2(a3);
            float i0 = fsig(A0.x), f0 = fsig(A1.x), gg0 = ftanh(A2.x), o0 = fsig(A3.x);
            float i1 = fsig(A0.y), f1 = fsig(A1.y), gg1 = ftanh(A2.y), o1 = fsig(A3.y);
            cc.x = f0 * cc.x + i0 * gg0;
            cc.y = f1 * cc.y + i1 * gg1;
            float2 hv = make_float2(o0 * ftanh(cc.x), o1 * ftanh(cc.y));
            *(float2*)&g_encT[(size_t)(t + 1) * 16384 + j * 32 + 2 * bp] = hv;
        }
        bar_arrive(g_arr0, (unsigned)(t + 1));
    }
}

// ------------------------- convolve + length mask ----------------------------
__global__ void conv_k(const int* __restrict__ lengths) {
    int t = blockIdx.x;
    int base = blockIdx.y * 2048;
#pragma unroll
    for (int p = 0; p < 8; p++) {
        int idx = base + p * 256 + threadIdx.x;
        int b = idx & 31;
        int len = lengths[b];
        float val = 0.f;
#pragma unroll
        for (int i = 0; i < 3; i++) {
            int tp = t - i;
            if (tp >= 0 && tp < len) {
                float a = g_attnT[((size_t)t * 3 + i) * 32 + b];
                val = fmaf(a, g_encT[(size_t)(tp + 1) * 16384 + idx], val);
            }
        }
        g_ctxT[(size_t)t * 16384 + idx] = val;
    }
}

// ------------------------- decoder output MLP -------------------------------
__device__ __forceinline__ void p_mlp(const float* __restrict__ hg, int bid, int tt,
                                      float* o1part, const float* bo1s, const float* wo2s,
                                      float bo2, float mval, float* __restrict__ outp,
                                      ull* flag, unsigned tag) {
    int w = tt >> 5, lane = tt & 31;
    int e = ((w & 3) << 5) + lane;
    int k0 = (w >> 2) << 8;
    const float* wo = g_wo1T + e;
    float s0 = 0.f, s1 = 0.f, s2 = 0.f, s3 = 0.f;
#pragma unroll 4
    for (int k = k0; k < k0 + 256; k += 4) {
        s0 = fmaf(wo[(size_t)(k + 0) * 128], hg[(k + 0) * 32 + bid], s0);
        s1 = fmaf(wo[(size_t)(k + 1) * 128], hg[(k + 1) * 32 + bid], s1);
        s2 = fmaf(wo[(size_t)(k + 2) * 128], hg[(k + 2) * 32 + bid], s2);
        s3 = fmaf(wo[(size_t)(k + 3) * 128], hg[(k + 3) * 32 + bid], s3);
    }
    o1part[((w >> 2) << 7) + e] = (s0 + s1) + (s2 + s3);
    __syncthreads();
    if (tt < 32) {
        float acc = 0.f;
#pragma unroll
        for (int m = 0; m < 4; m++) {
            int e2 = (m << 5) + tt;
            float v = fmaxf(o1part[e2] + o1part[128 + e2] + bo1s[e2], 0.f);
            acc = fmaf(v, wo2s[e2], acc);
        }
        acc += __shfl_xor_sync(0xffffffffu, acc, 16);
        acc += __shfl_xor_sync(0xffffffffu, acc, 8);
        acc += __shfl_xor_sync(0xffffffffu, acc, 4);
        acc += __shfl_xor_sync(0xffffffffu, acc, 2);
        acc += __shfl_xor_sync(0xffffffffu, acc, 1);
        if (tt == 0) {
            float p = acc + bo2;
            *outp = p * mval;
            if (flag)
                *((volatile ull*)flag) = ((ull)tag << 32) | (ull)__float_as_uint(p);
        }
    }
    __syncthreads();
}

// ------------------------- decoder LSTM (persistent, f32x2 packed) -----------
// quarters: q4 0,1 -> ctx dot halves (Wx); q4 2,3 -> h dot halves (Wh)
__global__ void __launch_bounds__(256, 1) dec_k(const float* __restrict__ Wih_d,
                                                const float* __restrict__ Whh_d,
                                                const float* __restrict__ bih_d,
                                                const float* __restrict__ bhh_d,
                                                const float* __restrict__ dec_c0,
                                                const float* __restrict__ b_o1,
                                                const float* __restrict__ W_o2,
                                                const float* __restrict__ b_o2,
                                                const float* __restrict__ mask,
                                                float* __restrict__ out) {
    float* Wxd = dsm;                     // 16 x 512 x 2 = 16384 floats
    float* Whd = dsm + 16384;             // 16 x 512 x 2 = 16384 floats
    __shared__ ull sredq[3 * 256];
    __shared__ ull bssq[16];
    __shared__ float w0s[16], o1part[256], bo1s[128], wo2s[128];
    int tt = threadIdx.x, bid = blockIdx.x;
    int bp = tt & 15, jl = (tt >> 4) & 3, q4 = tt >> 6;
    int j = bid * 4 + jl;
    for (int idx = tt; idx < 16 * 512; idx += 256) {
        int r = idx >> 9, k = idx & 511;
        int g = r & 3, jj = bid * 4 + (r >> 2);
        float wx = Wih_d[(size_t)(g * 512 + jj) * 513 + 1 + k];
        float wh = Whh_d[(size_t)(g * 512 + jj) * 512 + k];
        Wxd[r * 1024 + 2 * k] = wx; Wxd[r * 1024 + 2 * k + 1] = wx;
        Whd[r * 1024 + 2 * k] = wh; Whd[r * 1024 + 2 * k + 1] = wh;
    }
    if (tt < 16) {
        int g = tt & 3, jj = bid * 4 + (tt >> 2);
        int gr = g * 512 + jj;
        w0s[tt] = Wih_d[(size_t)gr * 513];
        bssq[tt] = dupf(bih_d[gr] + bhh_d[gr]);
    }
    if (bid < 32 && tt < 128) { bo1s[tt] = b_o1[tt]; wo2s[tt] = W_o2[tt]; }
    float2 cc;
    { float cv = dec_c0[j]; cc = make_float2(cv, cv); }
    const float* wbase = (q4 < 2) ? Wxd : Whd;
    const ulonglong2* W0 = (const ulonglong2*)&wbase[(jl * 4 + 0) * 1024];
    const ulonglong2* W1 = (const ulonglong2*)&wbase[(jl * 4 + 1) * 1024];
    const ulonglong2* W2 = (const ulonglong2*)&wbase[(jl * 4 + 2) * 1024];
    const ulonglong2* W3 = (const ulonglong2*)&wbase[(jl * 4 + 3) * 1024];
    int mbeg = (q4 & 1) * 128;
    float bo2v = b_o2[0];
    __syncthreads();
    for (int t = 0; t < 1024; t++) {
        if (t > 0) bar_wait(g_arr1, &g_go1, (unsigned)t);
        const float* hgl = g_hdecT + (size_t)t * 16384;   // h_{t-1}
        // batch blocks publish p_{t-1} before their gate dots
        if (bid < 32 && t > 0) {
            p_mlp(hgl, bid, tt, o1part, bo1s, wo2s, bo2v,
                  mask[bid * 1024 + (t - 1)], &out[bid * 1024 + (t - 1)],
                  &g_pq[bid], (unsigned)t);
        }
        ull a0, a1, a2, a3;
        if (q4 == 0) { a0 = bssq[jl * 4 + 0]; a1 = bssq[jl * 4 + 1]; a2 = bssq[jl * 4 + 2]; a3 = bssq[jl * 4 + 3]; }
        else { a0 = a1 = a2 = a3 = 0ull; }
        const float* srcb = (q4 < 2) ? (g_ctxT + (size_t)t * 16384) : hgl;
        const ull* hp = (const ull*)srcb + bp;
#pragma unroll 4
        for (int m = mbeg; m < mbeg + 128; m++) {
            ulonglong2 w0 = W0[m], w1 = W1[m], w2 = W2[m], w3 = W3[m];
            ull x0 = hp[(size_t)(2 * m) * 16];
            ull x1 = hp[(size_t)(2 * m + 1) * 16];
            FMA2(a0, w0.x, x0, a0); FMA2(a0, w0.y, x1, a0);
            FMA2(a1, w1.x, x0, a1); FMA2(a1, w1.y, x1, a1);
            FMA2(a2, w2.x, x0, a2); FMA2(a2, w2.y, x1, a2);
            FMA2(a3, w3.x, x0, a3); FMA2(a3, w3.y, x1, a3);
        }
        if (q4) {
            int o = ((q4 - 1) * 64 + (tt & 63)) * 4;
            sredq[o + 0] = a0; sredq[o + 1] = a1; sredq[o + 2] = a2; sredq[o + 3] = a3;
        }
        __syncthreads();
        if (q4 == 0) {
            int o = tt * 4;
#pragma unroll
            for (int r = 0; r < 3; r++) {
                ADD2(a0, a0, sredq[r * 256 + o + 0]);
                ADD2(a1, a1, sredq[r * 256 + o + 1]);
                ADD2(a2, a2, sredq[r * 256 + o + 2]);
                ADD2(a3, a3, sredq[r * 256 + o + 3]);
            }
            float2 A0 = u2f2(a0), A1 = u2f2(a1), A2 = u2f2(a2), A3 = u2f2(a3);
            if (t > 0) {
                ull q0v, q1v;
                do { q0v = *((volatile ull*)&g_pq[2 * bp]); } while ((unsigned)(q0v >> 32) != (unsigned)t);
                do { q1v = *((volatile ull*)&g_pq[2 * bp + 1]); } while ((unsigned)(q1v >> 32) != (unsigned)t);
                float p0 = __uint_as_float((unsigned)q0v);
                float p1 = __uint_as_float((unsigned)q1v);
                A0.x = fmaf(p0, w0s[jl * 4 + 0], A0.x); A0.y = fmaf(p1, w0s[jl * 4 + 0], A0.y);
                A1.x = fmaf(p0, w0s[jl * 4 + 1], A1.x); A1.y = fmaf(p1, w0s[jl * 4 + 1], A1.y);
                A2.x = fmaf(p0, w0s[jl * 4 + 2], A2.x); A2.y = fmaf(p1, w0s[jl * 4 + 2], A2.y);
                A3.x = fmaf(p0, w0s[jl * 4 + 3], A3.x); A3.y = fmaf(p1, w0s[jl * 4 + 3], A3.y);
            }
            float i0 = fsig(A0.x), f0 = fsig(A1.x), gg0 = ftanh(A2.x), o0 = fsig(A3.x);
            float i1 = fsig(A0.y), f1 = fsig(A1.y), gg1 = ftanh(A2.y), o1 = fsig(A3.y);
            cc.x = f0 * cc.x + i0 * gg0;
            cc.y = f1 * cc.y + i1 * gg1;
            float2 hv = make_float2(o0 * ftanh(cc.x), o1 * ftanh(cc.y));
            *(float2*)&g_hdecT[(size_t)(t + 1) * 16384 + j * 32 + 2 * bp] = hv;
        }
        bar_arrive(g_arr1, (unsigned)(t + 1));
    }
    // epilog: p_1023 from h slot 1024
    bar_wait(g_arr1, &g_go1, 1024u);
    if (bid < 32) {
        p_mlp(g_hdecT + (size_t)1024 * 16384, bid, tt, o1part, bo1s, wo2s, bo2v,
              mask[bid * 1024 + 1023], &out[bid * 1024 + 1023],
              (ull*)0, 0u);
    }
}

// ---------------------------------------------------------------------------
extern "C" void kernel_launch(void* const* d_in, const int* in_sizes, int n_in,
                              void* d_out, int out_size) {
    const float* inputs = (const float*)d_in[0];
    const float* mask   = (const float*)d_in[1];
    const int*   lengths= (const int*)d_in[2];
    const float* W_e    = (const float*)d_in[3];
    const float* b_e    = (const float*)d_in[4];
    const float* W_a1   = (const float*)d_in[5];
    const float* b_a1   = (const float*)d_in[6];
    const float* W_a2   = (const float*)d_in[7];
    const float* b_a2   = (const float*)d_in[8];
    const float* Wih_e  = (const float*)d_in[9];
    const float* Whh_e  = (const float*)d_in[10];
    const float* bih_e  = (const float*)d_in[11];
    const float* bhh_e  = (const float*)d_in[12];
    const float* enc_h0 = (const float*)d_in[13];
    const float* enc_c0 = (const float*)d_in[14];
    const float* Wih_d  = (const float*)d_in[15];
    const float* Whh_d  = (const float*)d_in[16];
    const float* bih_d  = (const float*)d_in[17];
    const float* bhh_d  = (const float*)d_in[18];
    const float* dec_h0 = (const float*)d_in[19];
    const float* dec_c0 = (const float*)d_in[20];
    const float* W_o1   = (const float*)d_in[21];
    const float* b_o1   = (const float*)d_in[22];
    const float* W_o2   = (const float*)d_in[23];
    const float* b_o2   = (const float*)d_in[24];
    float* out = (float*)d_out;

    cudaFuncSetAttribute(enc_k, cudaFuncAttributeMaxDynamicSharedMemorySize, 65536);
    cudaFuncSetAttribute(dec_k, cudaFuncAttributeMaxDynamicSharedMemorySize, 131072);

    void *p_embed, *p_a1v, *p_xp, *p_be;
    cudaGetSymbolAddress(&p_embed, g_embed);
    cudaGetSymbolAddress(&p_a1v, g_a1v);
    cudaGetSymbolAddress(&p_xp, g_xp);
    cudaGetSymbolAddress(&p_be, g_be);

    prep_k<<<8, 256>>>(bih_e, bhh_e);
    wo1t_k<<<256, 256>>>(W_o1);
    init_k<<<64, 256>>>(enc_h0, dec_h0);

    // embed = relu(inputs @ W_e^T + b_e)
    gemm_k<<<dim3(512, 2), 256>>>(inputs, W_e, b_e, (float*)p_embed, 32768, 128, 1024, 1);
    // a1 = relu(embed @ W_a1^T + b_a1)
    gemm_k<<<dim3(512, 2), 256>>>((const float*)p_embed, W_a1, b_a1, (float*)p_a1v, 32768, 128, 128, 1);
    // attention logits + softmax over time
    logits_k<<<128, 256>>>(W_a2, b_a2);
    softmax_k<<<dim3(32, 3), 256>>>();
    // x_proj = embed @ Wih_e^T + (bih_e + bhh_e)  (kept in (B*S,4H) layout)
    gemm_k<<<dim3(512, 32), 256>>>((const float*)p_embed, Wih_e, (const float*)p_be, (float*)p_xp, 32768, 2048, 128, 0);
    // encoder LSTM (persistent, packed f32x2, L1-cached unique-address reads)
    enc_k<<<128, 256, 65536>>>(Whh_e, enc_c0);
    // context = local attention over encoder outputs (with length mask)
    conv_k<<<dim3(1024, 8), 256>>>(lengths);
    // decoder LSTM + output MLP (persistent, packed f32x2)
    dec_k<<<128, 256, 131072>>>(Wih_d, Whh_d, bih_d, bhh_d, dec_c0,
                                b_o1, W_o2, b_o2, mask, out);
}

// round 17
// speedup vs baseline: 1.7097x; 1.7097x over previous
#include <cuda_runtime.h>
#include <math.h>
#include <stdint.h>
#include <stddef.h>

typedef unsigned long long ull;

// ---------------------------------------------------------------------------
// Shapes: B=32, S=1024, WIN=1024, E=128, H=512, L=3
// ---------------------------------------------------------------------------

// ------------------------- device scratch (no allocs) ----------------------
__device__ float g_embed[(size_t)32768 * 128];        // (B*S, E)
__device__ float g_a1v[(size_t)32768 * 128];          // (B*S, E)
__device__ float g_attn[(size_t)32768 * 3];           // logits (B*S, 3)
__device__ float g_attnT[(size_t)1024 * 3 * 32];      // [t][i][b] softmaxed
__device__ float g_xp[(size_t)32768 * 2048];          // (B*S, 4H) gate pre-act
__device__ float g_xpT[(size_t)1024 * 65536];         // [t][g*32+b]
__device__ float g_encT[(size_t)1025 * 16384];        // [t+1][j*32+b]; slot0 = h0
__device__ float g_ctxT[(size_t)1024 * 16384];        // [t][j*32+b]
__device__ float g_hdT[2][16384];                     // decoder h double buffer
__device__ float g_wo1T[512 * 128];                   // W_o1 transposed [k][e]
__device__ float g_be[2048];                          // bih_e + bhh_e
__device__ ull g_pq[32];                              // packed (tag<<32)|p_bits
__device__ unsigned g_arr0[128], g_arr1[128];
__device__ unsigned g_go0, g_go1;

// ------------------------- packed f32x2 helpers -----------------------------
#define FMA2(d, a, b, c) asm("fma.rn.f32x2 %0, %1, %2, %3;" : "=l"(d) : "l"(a), "l"(b), "l"(c))
#define ADD2(d, a, b)    asm("add.rn.f32x2 %0, %1, %2;"     : "=l"(d) : "l"(a), "l"(b))

__device__ __forceinline__ ull packf(float lo, float hi) {
    ull r;
    asm("mov.b64 %0, {%1, %2};" : "=l"(r) : "f"(lo), "f"(hi));
    return r;
}
__device__ __forceinline__ float2 u2f2(ull v) {
    float2 f;
    asm("mov.b64 {%0, %1}, %2;" : "=f"(f.x), "=f"(f.y) : "l"(v));
    return f;
}
__device__ __forceinline__ float fsig(float x) { return 1.0f / (1.0f + __expf(-x)); }
__device__ __forceinline__ float ftanh(float x) {
    float t = __expf(-2.0f * fabsf(x));
    return copysignf((1.0f - t) / (1.0f + t), x);
}

// ------------------------- split-phase grid barrier -------------------------
__device__ __forceinline__ void bar_arrive(unsigned* arr, unsigned tag) {
    __syncthreads();
    __threadfence();
    if (blockIdx.x != 0 && threadIdx.x == 0)
        *((volatile unsigned*)&arr[blockIdx.x]) = tag;
}

__device__ __forceinline__ void bar_wait(unsigned* arr, unsigned* go, unsigned tag) {
    if (blockIdx.x == 0) {
        if (threadIdx.x > 0 && threadIdx.x < 128) {
            while (*((volatile unsigned*)&arr[threadIdx.x]) < tag) {}
        }
        __syncthreads();
        if (threadIdx.x == 0) *((volatile unsigned*)go) = tag;
    } else {
        if (threadIdx.x == 0) {
            while (*((volatile unsigned*)go) < tag) {}
            __threadfence();
        }
        __syncthreads();
    }
}

// ------------------------- prep / init -------------------------------------
__global__ void prep_k(const float* __restrict__ bih_e, const float* __restrict__ bhh_e) {
    int n = blockIdx.x * 256 + threadIdx.x;
    if (n < 2048) g_be[n] = bih_e[n] + bhh_e[n];
}

__global__ void wo1t_k(const float* __restrict__ W_o1) {
    int n = blockIdx.x * 256 + threadIdx.x;   // 65536 elems
    int e = n >> 9, k = n & 511;
    g_wo1T[k * 128 + e] = W_o1[n];
}

__global__ void init_k(const float* __restrict__ enc_h0, const float* __restrict__ dec_h0) {
    int n = blockIdx.x * blockDim.x + threadIdx.x;
    int stride = gridDim.x * blockDim.x;
    if (n < 128) { g_arr0[n] = 0u; g_arr1[n] = 0u; }
    if (n < 32)  g_pq[n] = 0ull;
    if (n == 0) { g_go0 = 0u; g_go1 = 0u; }
    for (int e = n; e < 16384; e += stride) {
        g_encT[e]   = enc_h0[e >> 5];
        g_hdT[0][e] = dec_h0[e >> 5];
    }
}

// ------------------------- generic fp32 GEMM --------------------------------
__global__ void __launch_bounds__(256) gemm_k(const float* __restrict__ A,
                                              const float* __restrict__ W,
                                              const float* __restrict__ bias,
                                              float* __restrict__ C,
                                              int M, int N, int K, int relu) {
    __shared__ float As[16][72];
    __shared__ float Ws[16][72];
    int tid = threadIdx.x;
    int tx = tid & 15, ty = tid >> 4;
    int m0 = blockIdx.x * 64, n0 = blockIdx.y * 64;
    int lr = tid >> 2, lc = (tid & 3) << 2;
    const float* Ap = A + (size_t)(m0 + lr) * K + lc;
    const float* Wp = W + (size_t)(n0 + lr) * K + lc;
    float acc[4][4] = {};
    for (int k0 = 0; k0 < K; k0 += 16) {
        float4 a4 = *(const float4*)(Ap + k0);
        float4 w4 = *(const float4*)(Wp + k0);
        __syncthreads();
        As[lc + 0][lr] = a4.x; As[lc + 1][lr] = a4.y; As[lc + 2][lr] = a4.z; As[lc + 3][lr] = a4.w;
        Ws[lc + 0][lr] = w4.x; Ws[lc + 1][lr] = w4.y; Ws[lc + 2][lr] = w4.z; Ws[lc + 3][lr] = w4.w;
        __syncthreads();
#pragma unroll
        for (int kk = 0; kk < 16; kk++) {
            float4 av = *(const float4*)&As[kk][ty << 2];
            float4 wv = *(const float4*)&Ws[kk][tx << 2];
            acc[0][0] = fmaf(av.x, wv.x, acc[0][0]); acc[0][1] = fmaf(av.x, wv.y, acc[0][1]);
            acc[0][2] = fmaf(av.x, wv.z, acc[0][2]); acc[0][3] = fmaf(av.x, wv.w, acc[0][3]);
            acc[1][0] = fmaf(av.y, wv.x, acc[1][0]); acc[1][1] = fmaf(av.y, wv.y, acc[1][1]);
            acc[1][2] = fmaf(av.y, wv.z, acc[1][2]); acc[1][3] = fmaf(av.y, wv.w, acc[1][3]);
            acc[2][0] = fmaf(av.z, wv.x, acc[2][0]); acc[2][1] = fmaf(av.z, wv.y, acc[2][1]);
            acc[2][2] = fmaf(av.z, wv.z, acc[2][2]); acc[2][3] = fmaf(av.z, wv.w, acc[2][3]);
            acc[3][0] = fmaf(av.w, wv.x, acc[3][0]); acc[3][1] = fmaf(av.w, wv.y, acc[3][1]);
            acc[3][2] = fmaf(av.w, wv.z, acc[3][2]); acc[3][3] = fmaf(av.w, wv.w, acc[3][3]);
        }
    }
    float4 bz = *(const float4*)(bias + n0 + (tx << 2));
#pragma unroll
    for (int i = 0; i < 4; i++) {
        float4 o;
        o.x = acc[i][0] + bz.x; o.y = acc[i][1] + bz.y;
        o.z = acc[i][2] + bz.z; o.w = acc[i][3] + bz.w;
        if (relu) {
            o.x = fmaxf(o.x, 0.f); o.y = fmaxf(o.y, 0.f);
            o.z = fmaxf(o.z, 0.f); o.w = fmaxf(o.w, 0.f);
        }
        *(float4*)(C + (size_t)(m0 + (ty << 2) + i) * N + n0 + (tx << 2)) = o;
    }
}

// ------------------------- attention logits (L=3) ---------------------------
__global__ void logits_k(const float* __restrict__ W_a2, const float* __restrict__ b_a2) {
    __shared__ float w[3][128];
    int tt = threadIdx.x;
    if (tt < 128) { w[0][tt] = W_a2[tt]; w[1][tt] = W_a2[128 + tt]; w[2][tt] = W_a2[256 + tt]; }
    __syncthreads();
    int m = blockIdx.x * 256 + tt;
    const float* row = g_a1v + (size_t)m * 128;
    float s0 = b_a2[0], s1 = b_a2[1], s2 = b_a2[2];
#pragma unroll 4
    for (int k = 0; k < 128; k++) {
        float v = row[k];
        s0 = fmaf(v, w[0][k], s0);
        s1 = fmaf(v, w[1][k], s1);
        s2 = fmaf(v, w[2][k], s2);
    }
    g_attn[(size_t)m * 3 + 0] = s0;
    g_attn[(size_t)m * 3 + 1] = s1;
    g_attn[(size_t)m * 3 + 2] = s2;
}

// ------------------------- softmax over TIME (axis=1) -----------------------
__global__ void softmax_k() {
    int b = blockIdx.x, l = blockIdx.y, tt = threadIdx.x;
    __shared__ float red[256];
    float v[4];
    float mx = -1e30f;
#pragma unroll
    for (int i = 0; i < 4; i++) {
        int t = tt + i * 256;
        v[i] = g_attn[((size_t)b * 1024 + t) * 3 + l];
        mx = fmaxf(mx, v[i]);
    }
    red[tt] = mx; __syncthreads();
    for (int s = 128; s > 0; s >>= 1) { if (tt < s) red[tt] = fmaxf(red[tt], red[tt + s]); __syncthreads(); }
    mx = red[0]; __syncthreads();
    float sm = 0.f;
#pragma unroll
    for (int i = 0; i < 4; i++) { v[i] = expf(v[i] - mx); sm += v[i]; }
    red[tt] = sm; __syncthreads();
    for (int s = 128; s > 0; s >>= 1) { if (tt < s) red[tt] += red[tt + s]; __syncthreads(); }
    float inv = 1.f / red[0];
#pragma unroll
    for (int i = 0; i < 4; i++) {
        int t = tt + i * 256;
        g_attnT[((size_t)t * 3 + l) * 32 + b] = v[i] * inv;
    }
}

// ------------------------- x_proj transpose ---------------------------------
__global__ void transp_k() {
    __shared__ float tile[32][65];
    int t = blockIdx.x;
    int n0 = blockIdx.y * 64;
    int tt = threadIdx.x;
#pragma unroll
    for (int p = 0; p < 8; p++) {
        int e = p * 256 + tt;
        int b = e >> 6, nl = e & 63;
        tile[b][nl] = g_xp[((size_t)b * 1024 + t) * 2048 + n0 + nl];
    }
    __syncthreads();
#pragma unroll
    for (int p = 0; p < 8; p++) {
        int e = p * 256 + tt;
        int nl = e >> 5, b = e & 31;
        g_xpT[(size_t)t * 65536 + (size_t)(n0 + nl) * 32 + b] = tile[b][nl];
    }
}

// ------------------------- encoder LSTM (persistent, even/odd f32x2) --------
extern __shared__ float dsm[];
__global__ void __launch_bounds__(256, 1) enc_k(const float* __restrict__ Whh_e,
                                                const float* __restrict__ enc_c0) {
    float* Ws = dsm;             // 8192 floats  : 16 gate-rows x 512
    float* hs = dsm + 8192;      // 16384 floats : staged h [k*32+b]
    __shared__ ull sredq[512];
    int tt = threadIdx.x, bid = blockIdx.x;
    int b = tt & 31, jl = (tt >> 5) & 3, half = tt >> 7;
    int j = bid * 4 + jl;
    for (int idx = tt; idx < 16 * 128; idx += 256) {
        int r = idx >> 7, kk = (idx & 127) << 2;
        int q = r & 3, jj = bid * 4 + (r >> 2);
        *(float4*)&Ws[r * 512 + kk] = *(const float4*)&Whh_e[(size_t)(q * 512 + jj) * 512 + kk];
    }
    float c = (half == 0) ? enc_c0[j] : 0.f;
    const ulonglong2* w0q = (const ulonglong2*)&Ws[(jl * 4 + 0) * 512];
    const ulonglong2* w1q = (const ulonglong2*)&Ws[(jl * 4 + 1) * 512];
    const ulonglong2* w2q = (const ulonglong2*)&Ws[(jl * 4 + 2) * 512];
    const ulonglong2* w3q = (const ulonglong2*)&Ws[(jl * 4 + 3) * 512];
    int kqb = half * 64;                  // 64 ulonglong2-groups of 4 k each
    __syncthreads();
    for (int t = 0; t < 1024; t++) {
        // independent x-gate loads issued before the barrier wait
        float x0g = 0.f, x1g = 0.f, x2g = 0.f, x3g = 0.f;
        if (half == 0) {
            const float* xp = g_xpT + (size_t)t * 65536 + b;
            x0g = xp[(0 * 512 + j) * 32];
            x1g = xp[(1 * 512 + j) * 32];
            x2g = xp[(2 * 512 + j) * 32];
            x3g = xp[(3 * 512 + j) * 32];
        }
        if (t > 0) bar_wait(g_arr0, &g_go0, (unsigned)t);
        // stage h_t into smem (unique addresses per t -> plain ld)
        {
            const float4* src = (const float4*)(g_encT + (size_t)t * 16384);
            float4* dst = (float4*)hs;
#pragma unroll
            for (int i = tt; i < 4096; i += 256) dst[i] = src[i];
        }
        __syncthreads();
        ull a0q = packf(x0g, 0.f), a1q = packf(x1g, 0.f);
        ull a2q = packf(x2g, 0.f), a3q = packf(x3g, 0.f);
        const float* hp = hs + b;
#pragma unroll 4
        for (int kq = kqb; kq < kqb + 64; kq++) {
            ulonglong2 w0 = w0q[kq], w1 = w1q[kq], w2 = w2q[kq], w3 = w3q[kq];
            const float* xp2 = hp + (kq << 2) * 32;
            ull xa = packf(xp2[0], xp2[32]);
            ull xb = packf(xp2[64], xp2[96]);
            FMA2(a0q, w0.x, xa, a0q); FMA2(a0q, w0.y, xb, a0q);
            FMA2(a1q, w1.x, xa, a1q); FMA2(a1q, w1.y, xb, a1q);
            FMA2(a2q, w2.x, xa, a2q); FMA2(a2q, w2.y, xb, a2q);
            FMA2(a3q, w3.x, xa, a3q); FMA2(a3q, w3.y, xb, a3q);
        }
        if (half) {
            int o = (tt - 128) << 2;
            sredq[o + 0] = a0q; sredq[o + 1] = a1q; sredq[o + 2] = a2q; sredq[o + 3] = a3q;
        }
        __syncthreads();
        if (!half) {
            int o = tt << 2;
            ADD2(a0q, a0q, sredq[o + 0]);
            ADD2(a1q, a1q, sredq[o + 1]);
            ADD2(a2q, a2q, sredq[o + 2]);
            ADD2(a3q, a3q, sredq[o + 3]);
            float2 A0 = u2f2(a0q), A1 = u2f2(a1q), A2 = u2f2(a2q), A3 = u2f2(a3q);
            float a0 = A0.x + A0.y, a1 = A1.x + A1.y, a2 = A2.x + A2.y, a3 = A3.x + A3.y;
            float ig = fsig(a0), fg = fsig(a1), gg = ftanh(a2), og = fsig(a3);
            c = fg * c + ig * gg;
            g_encT[(size_t)(t + 1) * 16384 + j * 32 + b] = og * ftanh(c);
        }
        bar_arrive(g_arr0, (unsigned)(t + 1));
    }
}

// ------------------------- convolve + length mask ----------------------------
__global__ void conv_k(const int* __restrict__ lengths) {
    int t = blockIdx.x;
    int base = blockIdx.y * 2048;
#pragma unroll
    for (int p = 0; p < 8; p++) {
        int idx = base + p * 256 + threadIdx.x;
        int b = idx & 31;
        int len = lengths[b];
        float val = 0.f;
#pragma unroll
        for (int i = 0; i < 3; i++) {
            int tp = t - i;
            if (tp >= 0 && tp < len) {
                float a = g_attnT[((size_t)t * 3 + i) * 32 + b];
                val = fmaf(a, g_encT[(size_t)(tp + 1) * 16384 + idx], val);
            }
        }
        g_ctxT[(size_t)t * 16384 + idx] = val;
    }
}

// ------------------------- decoder LSTM + out MLP (persistent) ---------------
__global__ void __launch_bounds__(256, 1) dec_k(const float* __restrict__ Wih_d,
                                                const float* __restrict__ Whh_d,
                                                const float* __restrict__ bih_d,
                                                const float* __restrict__ bhh_d,
                                                const float* __restrict__ dec_c0,
                                                const float* __restrict__ b_o1,
                                                const float* __restrict__ W_o2,
                                                const float* __restrict__ b_o2,
                                                const float* __restrict__ mask,
                                                float* __restrict__ out) {
    float* Wxs = dsm;             // 8192  : Wih_d[:,1:513] gate rows
    float* Whs = dsm + 8192;      // 8192  : Whh_d gate rows
    float* hs  = dsm + 16384;     // 16384 : staged h_{t-1} [k*32+b]
    float* cs  = dsm + 32768;     // 16384 : staged ctx_t   [k*32+b]
    __shared__ ull sredq[512];
    __shared__ float o1part[256];
    __shared__ float w0s[16], bss[16], wo2s[128], bo1s[128];
    int tt = threadIdx.x, bid = blockIdx.x;
    int b = tt & 31, jl = (tt >> 5) & 3, half = tt >> 7;
    int j = bid * 4 + jl;
    for (int idx = tt; idx < 16 * 512; idx += 256) {
        int r = idx >> 9, k = idx & 511;
        int q = r & 3, jj = bid * 4 + (r >> 2);
        Wxs[idx] = Wih_d[(size_t)(q * 512 + jj) * 513 + 1 + k];
    }
    for (int idx = tt; idx < 16 * 128; idx += 256) {
        int r = idx >> 7, kk = (idx & 127) << 2;
        int q = r & 3, jj = bid * 4 + (r >> 2);
        *(float4*)&Whs[r * 512 + kk] = *(const float4*)&Whh_d[(size_t)(q * 512 + jj) * 512 + kk];
    }
    if (tt < 16) {
        int q = tt & 3, jj = bid * 4 + (tt >> 2);
        int g = q * 512 + jj;
        w0s[tt] = Wih_d[(size_t)g * 513];
        bss[tt] = bih_d[g] + bhh_d[g];
    }
    if (bid < 32 && tt < 128) { bo1s[tt] = b_o1[tt]; wo2s[tt] = W_o2[tt]; }
    float c = (half == 0) ? dec_c0[j] : 0.f;
    const float* wbase = half ? Whs : Wxs;
    const ulonglong2* w0q = (const ulonglong2*)&wbase[(jl * 4 + 0) * 512];
    const ulonglong2* w1q = (const ulonglong2*)&wbase[(jl * 4 + 1) * 512];
    const ulonglong2* w2q = (const ulonglong2*)&wbase[(jl * 4 + 2) * 512];
    const ulonglong2* w3q = (const ulonglong2*)&wbase[(jl * 4 + 3) * 512];
    float bo2v = b_o2[0];
    __syncthreads();
    int par = 0;
    for (int t = 0; t < 1024; t++) {
        // stage ctx_t (independent of the barrier -> hides barrier latency)
        {
            const float4* cg = (const float4*)(g_ctxT + (size_t)t * 16384);
            float4* cd = (float4*)cs;
#pragma unroll
            for (int i = tt; i < 4096; i += 256) cd[i] = cg[i];
        }
        if (t > 0) bar_wait(g_arr1, &g_go1, (unsigned)t);
        // stage h_{t-1} (reused buffer -> must bypass L1)
        {
            const float4* hg = (const float4*)(g_hdT[par]);
            float4* hd = (float4*)hs;
#pragma unroll
            for (int i = tt; i < 4096; i += 256) hd[i] = __ldcg(&hg[i]);
        }
        __syncthreads();
        // batch blocks publish p_{t-1} BEFORE their gate dots
        if (bid < 32 && t > 0) {
            int w = tt >> 5, lane = tt & 31;
            int e = ((w & 3) << 5) + lane;
            int k0 = (w >> 2) << 8;
            float s0 = 0.f, s1 = 0.f, s2 = 0.f, s3 = 0.f;
            const float* wo = g_wo1T + e;
#pragma unroll 4
            for (int k = k0; k < k0 + 256; k += 4) {
                s0 = fmaf(wo[(size_t)(k + 0) * 128], hs[(k + 0) * 32 + bid], s0);
                s1 = fmaf(wo[(size_t)(k + 1) * 128], hs[(k + 1) * 32 + bid], s1);
                s2 = fmaf(wo[(size_t)(k + 2) * 128], hs[(k + 2) * 32 + bid], s2);
                s3 = fmaf(wo[(size_t)(k + 3) * 128], hs[(k + 3) * 32 + bid], s3);
            }
            o1part[((w >> 2) << 7) + e] = (s0 + s1) + (s2 + s3);
            __syncthreads();
            if (tt < 32) {
                float acc = 0.f;
#pragma unroll
                for (int m = 0; m < 4; m++) {
                    int e2 = (m << 5) + tt;
                    float v = fmaxf(o1part[e2] + o1part[128 + e2] + bo1s[e2], 0.f);
                    acc = fmaf(v, wo2s[e2], acc);
                }
                acc += __shfl_xor_sync(0xffffffffu, acc, 16);
                acc += __shfl_xor_sync(0xffffffffu, acc, 8);
                acc += __shfl_xor_sync(0xffffffffu, acc, 4);
                acc += __shfl_xor_sync(0xffffffffu, acc, 2);
                acc += __shfl_xor_sync(0xffffffffu, acc, 1);
                if (tt == 0) {
                    float p = acc + bo2v;
                    out[bid * 1024 + (t - 1)] = p * mask[bid * 1024 + (t - 1)];
                    ull q = ((ull)(unsigned)t << 32) | (ull)__float_as_uint(p);
                    *((volatile ull*)&g_pq[bid]) = q;
                }
            }
        }
        // gate dots: half0 = ctx part (Wx, + bias), half1 = h part (Wh)
        float binit = half ? 0.f : bss[jl * 4 + 0];
        ull a0q = packf(binit, 0.f);
        ull a1q = packf(half ? 0.f : bss[jl * 4 + 1], 0.f);
        ull a2q = packf(half ? 0.f : bss[jl * 4 + 2], 0.f);
        ull a3q = packf(half ? 0.f : bss[jl * 4 + 3], 0.f);
        {
            const float* src = (half ? hs : cs) + b;
#pragma unroll 4
            for (int kq = 0; kq < 128; kq++) {
                ulonglong2 w0 = w0q[kq], w1 = w1q[kq], w2 = w2q[kq], w3 = w3q[kq];
                const float* xp2 = src + (kq << 2) * 32;
                ull xa = packf(xp2[0], xp2[32]);
                ull xb = packf(xp2[64], xp2[96]);
                FMA2(a0q, w0.x, xa, a0q); FMA2(a0q, w0.y, xb, a0q);
                FMA2(a1q, w1.x, xa, a1q); FMA2(a1q, w1.y, xb, a1q);
                FMA2(a2q, w2.x, xa, a2q); FMA2(a2q, w2.y, xb, a2q);
                FMA2(a3q, w3.x, xa, a3q); FMA2(a3q, w3.y, xb, a3q);
            }
        }
        if (half) {
            int o = (tt - 128) << 2;
            sredq[o + 0] = a0q; sredq[o + 1] = a1q; sredq[o + 2] = a2q; sredq[o + 3] = a3q;
        }
        __syncthreads();
        if (!half) {
            int o = tt << 2;
            ADD2(a0q, a0q, sredq[o + 0]);
            ADD2(a1q, a1q, sredq[o + 1]);
            ADD2(a2q, a2q, sredq[o + 2]);
            ADD2(a3q, a3q, sredq[o + 3]);
            float2 A0 = u2f2(a0q), A1 = u2f2(a1q), A2 = u2f2(a2q), A3 = u2f2(a3q);
            float a0 = A0.x + A0.y, a1 = A1.x + A1.y, a2 = A2.x + A2.y, a3 = A3.x + A3.y;
            // late rank-1 p term: poll the packed flag (usually long ready)
            if (t > 0) {
                ull q;
                do { q = *((volatile ull*)&g_pq[b]); }
                while ((unsigned)(q >> 32) != (unsigned)t);
                float pv = __uint_as_float((unsigned)q);
                a0 = fmaf(pv, w0s[jl * 4 + 0], a0);
                a1 = fmaf(pv, w0s[jl * 4 + 1], a1);
                a2 = fmaf(pv, w0s[jl * 4 + 2], a2);
                a3 = fmaf(pv, w0s[jl * 4 + 3], a3);
            }
            float ig = fsig(a0), fg = fsig(a1), gg = ftanh(a2), og = fsig(a3);
            c = fg * c + ig * gg;
            g_hdT[par ^ 1][j * 32 + b] = og * ftanh(c);
        }
        bar_arrive(g_arr1, (unsigned)(t + 1));
        par ^= 1;
    }
    // ---- epilog: p_1023 from h_1023 (batch blocks; block0 serves barrier) ----
    bar_wait(g_arr1, &g_go1, 1024u);
    if (bid < 32) {
        {
            const float4* hg = (const float4*)(g_hdT[par]);
            float4* hd = (float4*)hs;
#pragma unroll
            for (int i = tt; i < 4096; i += 256) hd[i] = __ldcg(&hg[i]);
        }
        __syncthreads();
        int w = tt >> 5, lane = tt & 31;
        int e = ((w & 3) << 5) + lane;
        int k0 = (w >> 2) << 8;
        float s0 = 0.f, s1 = 0.f, s2 = 0.f, s3 = 0.f;
        const float* wo = g_wo1T + e;
#pragma unroll 4
        for (int k = k0; k < k0 + 256; k += 4) {
            s0 = fmaf(wo[(size_t)(k + 0) * 128], hs[(k + 0) * 32 + bid], s0);
            s1 = fmaf(wo[(size_t)(k + 1) * 128], hs[(k + 1) * 32 + bid], s1);
            s2 = fmaf(wo[(size_t)(k + 2) * 128], hs[(k + 2) * 32 + bid], s2);
            s3 = fmaf(wo[(size_t)(k + 3) * 128], hs[(k + 3) * 32 + bid], s3);
        }
        o1part[((w >> 2) << 7) + e] = (s0 + s1) + (s2 + s3);
        __syncthreads();
        if (tt < 32) {
            float acc = 0.f;
#pragma unroll
            for (int m = 0; m < 4; m++) {
                int e2 = (m << 5) + tt;
                float v = fmaxf(o1part[e2] + o1part[128 + e2] + bo1s[e2], 0.f);
                acc = fmaf(v, wo2s[e2], acc);
            }
            acc += __shfl_xor_sync(0xffffffffu, acc, 16);
            acc += __shfl_xor_sync(0xffffffffu, acc, 8);
            acc += __shfl_xor_sync(0xffffffffu, acc, 4);
            acc += __shfl_xor_sync(0xffffffffu, acc, 2);
            acc += __shfl_xor_sync(0xffffffffu, acc, 1);
            if (tt == 0) {
                float p = acc + bo2v;
                out[bid * 1024 + 1023] = p * mask[bid * 1024 + 1023];
            }
        }
    }
}

// ---------------------------------------------------------------------------
extern "C" void kernel_launch(void* const* d_in, const int* in_sizes, int n_in,
                              void* d_out, int out_size) {
    const float* inputs = (const float*)d_in[0];
    const float* mask   = (const float*)d_in[1];
    const int*   lengths= (const int*)d_in[2];
    const float* W_e    = (const float*)d_in[3];
    const float* b_e    = (const float*)d_in[4];
    const float* W_a1   = (const float*)d_in[5];
    const float* b_a1   = (const float*)d_in[6];
    const float* W_a2   = (const float*)d_in[7];
    const float* b_a2   = (const float*)d_in[8];
    const float* Wih_e  = (const float*)d_in[9];
    const float* Whh_e  = (const float*)d_in[10];
    const float* bih_e  = (const float*)d_in[11];
    const float* bhh_e  = (const float*)d_in[12];
    const float* enc_h0 = (const float*)d_in[13];
    const float* enc_c0 = (const float*)d_in[14];
    const float* Wih_d  = (const float*)d_in[15];
    const float* Whh_d  = (const float*)d_in[16];
    const float* bih_d  = (const float*)d_in[17];
    const float* bhh_d  = (const float*)d_in[18];
    const float* dec_h0 = (const float*)d_in[19];
    const float* dec_c0 = (const float*)d_in[20];
    const float* W_o1   = (const float*)d_in[21];
    const float* b_o1   = (const float*)d_in[22];
    const float* W_o2   = (const float*)d_in[23];
    const float* b_o2   = (const float*)d_in[24];
    float* out = (float*)d_out;

    cudaFuncSetAttribute(enc_k, cudaFuncAttributeMaxDynamicSharedMemorySize, 98304);
    cudaFuncSetAttribute(dec_k, cudaFuncAttributeMaxDynamicSharedMemorySize, 196608);

    void *p_embed, *p_a1v, *p_xp, *p_be;
    cudaGetSymbolAddress(&p_embed, g_embed);
    cudaGetSymbolAddress(&p_a1v, g_a1v);
    cudaGetSymbolAddress(&p_xp, g_xp);
    cudaGetSymbolAddress(&p_be, g_be);

    prep_k<<<8, 256>>>(bih_e, bhh_e);
    wo1t_k<<<256, 256>>>(W_o1);
    init_k<<<64, 256>>>(enc_h0, dec_h0);

    // embed = relu(inputs @ W_e^T + b_e)
    gemm_k<<<dim3(512, 2), 256>>>(inputs, W_e, b_e, (float*)p_embed, 32768, 128, 1024, 1);
    // a1 = relu(embed @ W_a1^T + b_a1)
    gemm_k<<<dim3(512, 2), 256>>>((const float*)p_embed, W_a1, b_a1, (float*)p_a1v, 32768, 128, 128, 1);
    // attention logits + softmax over time
    logits_k<<<128, 256>>>(W_a2, b_a2);
    softmax_k<<<dim3(32, 3), 256>>>();
    // x_proj = embed @ Wih_e^T + (bih_e + bhh_e)
    gemm_k<<<dim3(512, 32), 256>>>((const float*)p_embed, Wih_e, (const float*)p_be, (float*)p_xp, 32768, 2048, 128, 0);
    transp_k<<<dim3(1024, 32), 256>>>();
    // encoder LSTM (persistent, staged SMEM + even/odd f32x2 dots)
    enc_k<<<128, 256, 98304>>>(Whh_e, enc_c0);
    // context = local attention over encoder outputs (with length mask)
    conv_k<<<dim3(1024, 8), 256>>>(lengths);
    // decoder LSTM + output MLP (persistent, staged SMEM + even/odd f32x2 dots)
    dec_k<<<128, 256, 196608>>>(Wih_d, Whh_d, bih_d, bhh_d, dec_c0,
                                b_o1, W_o2, b_o2, mask, out);
}